// round 15
// baseline (speedup 1.0000x reference)
#include <cuda_runtime.h>
#include <cuda_fp16.h>
#include <cstdint>

#define BATCH 4
#define SEQ   2048
#define DMODEL 1024
#define NHEAD 16
#define DHEAD 64
#define NTOK  (BATCH*SEQ)   // 8192
#define MM    (DMODEL*DMODEL)
#define LOG2E 1.44269504088896f

// ---------------- scratch (__device__ globals: allocation-free) ----------------
__device__ __align__(16) __half g_Ahi[NTOK*DMODEL];
__device__ __align__(16) __half g_WhT[4*MM];          // [N,K] transposed fp16
__device__ __align__(16) __half g_Qhi[NTOK*DMODEL];   // pre-scaled by 0.125*log2(e)
__device__ __align__(16) __half g_Khi[NTOK*DMODEL];
__device__ __align__(16) __half g_Vhi[NTOK*DMODEL];
__device__ __align__(16) __half g_Zhi[NTOK*DMODEL];

__device__ __forceinline__ uint32_t smem_u32(const void* p) {
    uint32_t a;
    asm("{ .reg .u64 t; cvta.to.shared.u64 t, %1; cvt.u32.u64 %0, t; }" : "=r"(a) : "l"(p));
    return a;
}

#define MMA_F16(acc, a, b) \
    asm volatile("mma.sync.aligned.m16n8k16.row.col.f32.f16.f16.f32 " \
        "{%0,%1,%2,%3}, {%4,%5,%6,%7}, {%8,%9}, {%0,%1,%2,%3};" \
        : "+f"((acc)[0]), "+f"((acc)[1]), "+f"((acc)[2]), "+f"((acc)[3]) \
        : "r"((a)[0]), "r"((a)[1]), "r"((a)[2]), "r"((a)[3]), "r"((b)[0]), "r"((b)[1]))

#define LDSM_X4_TRANS(r0, r1, r2, r3, addr) \
    asm volatile("ldmatrix.sync.aligned.m8n8.x4.trans.shared.b16 {%0,%1,%2,%3}, [%4];" \
        : "=r"(r0), "=r"(r1), "=r"(r2), "=r"(r3) : "r"(addr))

#define CPA16(dst, src) \
    asm volatile("cp.async.cg.shared.global [%0], [%1], 16;" :: "r"(dst), "l"(src) : "memory")

// ---------------- conversion kernels ----------------
__global__ void __launch_bounds__(256) conv_resid(const float* __restrict__ src) {
    int i = blockIdx.x * 256 + threadIdx.x;
    float4 v = ((const float4*)src)[i];
    ((__half2*)g_Ahi)[2*i]   = __floats2half2_rn(v.x, v.y);
    ((__half2*)g_Ahi)[2*i+1] = __floats2half2_rn(v.z, v.w);
}

// All 4 weights in one launch: blockIdx.z = widx; widx==3 applies [dh,h,d] row remap.
__global__ void __launch_bounds__(1024) conv_W4(const float* __restrict__ WQ,
                                                const float* __restrict__ WK,
                                                const float* __restrict__ WV,
                                                const float* __restrict__ WO) {
    __shared__ float t[32][33];
    int widx = blockIdx.z;
    const float* src = (widx == 0) ? WQ : (widx == 1) ? WK : (widx == 2) ? WV : WO;
    int tx = threadIdx.x, ty = threadIdx.y;
    int k = blockIdx.y * 32 + ty, n = blockIdx.x * 32 + tx;
    int sk = (widx == 3) ? ((k & 63) * 16 + (k >> 6)) : k;
    t[ty][tx] = src[sk * DMODEL + n];
    __syncthreads();
    int n2 = blockIdx.x * 32 + ty, k2 = blockIdx.y * 32 + tx;
    g_WhT[(size_t)widx * MM + (size_t)n2 * DMODEL + k2] = __float2half_rn(t[tx][ty]);
}

// ---------------- 1-pass fp16 HMMA GEMM: C = alpha*(A@Bh^T), KC=64 ----------------
#define KC    64
#define NCH   (DMODEL / KC)            // 16
#define NSTG  3
#define ROWB  144                      // 128 data + 16 pad
#define TILE_B (128 * ROWB)            // 18432
#define STG_B  (2 * TILE_B)            // A, B
#define GEMM_SMEM (NSTG * STG_B)       // 110592

__device__ __forceinline__ void load_tile(uint32_t sdst, const __half* __restrict__ g,
                                          int row0, int k0, int tid) {
    const char* gb = (const char*)(g + (size_t)row0 * DMODEL + k0);
    #pragma unroll
    for (int i = 0; i < 4; i++) {
        int id = i * 256 + tid;
        int r = id >> 3, c = id & 7;
        uint32_t sd = sdst + (uint32_t)(r * ROWB + c * 16);
        const char* gp = gb + (size_t)r * (DMODEL * 2) + c * 16;
        CPA16(sd, gp);
    }
}

// OUTMODE 0: fp32 C + bias; 2: fp16 output. Single-sync multistage mainloop.
template<int OUTMODE>
__device__ __forceinline__ void gemm_hmma(const __half* __restrict__ A,
                                          const __half* __restrict__ Bh,
                                          float* __restrict__ C,
                                          const float* __restrict__ bias,
                                          __half* __restrict__ Chi,
                                          float alpha)
{
    extern __shared__ char sm[];
    uint32_t sbase = smem_u32(sm);

    int tid  = threadIdx.x;
    int wid  = tid >> 5, lane = tid & 31;
    int gr   = lane >> 2;
    int lc2  = (lane & 3) * 2;
    int wm   = (wid & 3) * 32;
    int wn   = (wid >> 2) * 64;
    int brow = blockIdx.y * 128;
    int bcol = blockIdx.x * 128;

    float acc[2][8][4];
    #pragma unroll
    for (int i = 0; i < 2; i++)
        #pragma unroll
        for (int j = 0; j < 8; j++)
            #pragma unroll
            for (int q = 0; q < 4; q++) acc[i][j][q] = 0.f;

    #pragma unroll
    for (int s = 0; s < NSTG - 1; s++) {
        uint32_t stg = sbase + s * STG_B;
        int k0 = s * KC;
        load_tile(stg,          A,  brow, k0, tid);
        load_tile(stg + TILE_B, Bh, bcol, k0, tid);
        asm volatile("cp.async.commit_group;" ::: "memory");
    }

    for (int c = 0; c < NCH; c++) {
        int rem = NCH - 1 - c;
        if (rem >= 1) asm volatile("cp.async.wait_group 1;" ::: "memory");
        else          asm volatile("cp.async.wait_group 0;" ::: "memory");
        __syncthreads();

        const char* stg = sm + (size_t)(c % NSTG) * STG_B;
        const char* pA  = stg;
        const char* pBh = stg + TILE_B;

        #pragma unroll
        for (int ks = 0; ks < 4; ks++) {
            int k0b = ks * 32;
            uint32_t ah[2][4], bh[8][2];
            #pragma unroll
            for (int mt = 0; mt < 2; mt++) {
                const char* p = pA + (wm + mt*16 + gr) * ROWB + k0b + lc2*2;
                ah[mt][0] = *(const uint32_t*)p;
                ah[mt][1] = *(const uint32_t*)(p + 8*ROWB);
                ah[mt][2] = *(const uint32_t*)(p + 16);
                ah[mt][3] = *(const uint32_t*)(p + 8*ROWB + 16);
            }
            #pragma unroll
            for (int nt = 0; nt < 8; nt++) {
                const char* p = pBh + (wn + nt*8 + gr) * ROWB + k0b + lc2*2;
                bh[nt][0] = *(const uint32_t*)p;
                bh[nt][1] = *(const uint32_t*)(p + 16);
            }
            #pragma unroll
            for (int mt = 0; mt < 2; mt++)
                #pragma unroll
                for (int nt = 0; nt < 8; nt++)
                    MMA_F16(acc[mt][nt], ah[mt], bh[nt]);
        }

        int cn = c + NSTG - 1;
        if (cn < NCH) {
            uint32_t stg2 = sbase + (cn % NSTG) * STG_B;
            int k0 = cn * KC;
            load_tile(stg2,          A,  brow, k0, tid);
            load_tile(stg2 + TILE_B, Bh, bcol, k0, tid);
            asm volatile("cp.async.commit_group;" ::: "memory");
        }
    }

    #pragma unroll
    for (int mt = 0; mt < 2; mt++) {
        int r0 = brow + wm + mt*16 + gr;
        #pragma unroll
        for (int nt = 0; nt < 8; nt++) {
            int c0 = bcol + wn + nt*8 + lc2;
            if (OUTMODE == 0) {
                float bx = bias[c0], by = bias[c0 + 1];
                float2 v0, v1;
                v0.x = acc[mt][nt][0] * alpha + bx;
                v0.y = acc[mt][nt][1] * alpha + by;
                v1.x = acc[mt][nt][2] * alpha + bx;
                v1.y = acc[mt][nt][3] * alpha + by;
                *(float2*)&C[(size_t)r0 * DMODEL + c0]       = v0;
                *(float2*)&C[(size_t)(r0 + 8) * DMODEL + c0] = v1;
            } else {
                *(__half2*)&Chi[(size_t)r0 * DMODEL + c0] =
                    __floats2half2_rn(acc[mt][nt][0] * alpha, acc[mt][nt][1] * alpha);
                *(__half2*)&Chi[(size_t)(r0+8) * DMODEL + c0] =
                    __floats2half2_rn(acc[mt][nt][2] * alpha, acc[mt][nt][3] * alpha);
            }
        }
    }
}

__global__ void __launch_bounds__(256, 2) qkv_tc_kernel() {
    int z = blockIdx.z;
    const __half* Bh = g_WhT + (size_t)z * MM;
    __half* Ch = (z == 0) ? g_Qhi : (z == 1) ? g_Khi : g_Vhi;
    float alpha = (z == 0) ? (0.125f * LOG2E) : 1.0f;
    gemm_hmma<2>(g_Ahi, Bh, nullptr, nullptr, Ch, alpha);
}

__global__ void __launch_bounds__(256, 2) out_tc_kernel(const float* __restrict__ bias,
                                                        float* __restrict__ out) {
    gemm_hmma<0>(g_Zhi, g_WhT + 3ull*MM, out, bias, nullptr, 1.0f);
}

// ---------------- fp16 flash attention (causal); h2exp2 softmax, Q in registers ----------------
#define AROW 144
#define QREG (128 * AROW)
#define TREG (64 * AROW)
#define STAGE2 (2 * TREG)                  // Khi, Vhi (natural layout)
#define ASTG 3
#define ATT2_SMEM (QREG + ASTG*STAGE2)     // 73728

__device__ __forceinline__ void load_att_stage(uint32_t dst, int b, int h, int kt, int tid) {
    int s0 = kt * 64;
    const char* gkh = (const char*)g_Khi + ((size_t)(b*SEQ + s0) * DMODEL + h*64) * 2;
    const char* gvh = (const char*)g_Vhi + ((size_t)(b*SEQ + s0) * DMODEL + h*64) * 2;
    #pragma unroll
    for (int i = 0; i < 2; i++) {
        int idx = i * 256 + tid;
        int r = idx >> 3, c = idx & 7;
        uint32_t off = (uint32_t)(r * AROW + c * 16);
        CPA16(dst + off,        gkh + (size_t)r * (DMODEL*2) + c*16);
        CPA16(dst + TREG + off, gvh + (size_t)r * (DMODEL*2) + c*16);
    }
}

__global__ void __launch_bounds__(256, 2) attn2_kernel() {
    extern __shared__ char sm[];
    uint32_t sq = smem_u32(sm);

    int tid = threadIdx.x, wid = tid >> 5, lane = tid & 31;
    int gr = lane >> 2, lq = (lane & 3) * 2;
    int qt = (gridDim.x - 1) - blockIdx.x;   // heaviest CTAs first
    int h = blockIdx.y, b = blockIdx.z;
    int q0 = qt * 128, wm = wid * 16;
    int nkt = 2*qt + 2;

    uint32_t vloff = (uint32_t)(((lane & 7) + ((lane >> 3) & 1) * 8) * AROW + (lane >> 4) * 16);

    {
        const char* gqh = (const char*)g_Qhi + ((size_t)(b*SEQ + q0) * DMODEL + h*64) * 2;
        #pragma unroll
        for (int i = 0; i < 4; i++) {
            int idx = i * 256 + tid;
            int r = idx >> 3, c = idx & 7;
            uint32_t off = (uint32_t)(r * AROW + c * 16);
            CPA16(sq + off, gqh + (size_t)r * (DMODEL*2) + c*16);
        }
    }
    load_att_stage(sq + QREG, b, h, 0, tid);
    asm volatile("cp.async.commit_group;" ::: "memory");
    if (nkt > 1) {
        load_att_stage(sq + QREG + STAGE2, b, h, 1, tid);
        asm volatile("cp.async.commit_group;" ::: "memory");
    }

    float m0 = -1e30f, m1 = -1e30f, l0 = 0.f, l1 = 0.f;
    float O[8][4];
    #pragma unroll
    for (int i = 0; i < 8; i++)
        #pragma unroll
        for (int j = 0; j < 4; j++) O[i][j] = 0.f;

    uint32_t qreg[4][4];   // Q fragments, loop-invariant (loaded at kt==0)
    int r0g = q0 + wm + gr, r1g = r0g + 8;

    for (int kt = 0; kt < nkt; kt++) {
        int rem = nkt - 1 - kt;
        if (rem >= 1) asm volatile("cp.async.wait_group 1;" ::: "memory");
        else          asm volatile("cp.async.wait_group 0;" ::: "memory");
        __syncthreads();

        if (kt == 0) {
            #pragma unroll
            for (int ks = 0; ks < 4; ks++) {
                const char* pa = sm + (wm + gr) * AROW + ks*32 + lq*2;
                qreg[ks][0] = *(const uint32_t*)pa;
                qreg[ks][1] = *(const uint32_t*)(pa + 8*AROW);
                qreg[ks][2] = *(const uint32_t*)(pa + 16);
                qreg[ks][3] = *(const uint32_t*)(pa + 8*AROW + 16);
            }
        }

        int s0 = kt * 64;
        if (s0 <= q0 + wm + 15) {
            const char* st   = sm + QREG + (size_t)(kt % ASTG) * STAGE2;
            const char* kh   = st;
            uint32_t vbase   = sq + QREG + (uint32_t)(kt % ASTG) * STAGE2 + TREG + vloff;

            float S[8][4];
            #pragma unroll
            for (int i = 0; i < 8; i++)
                #pragma unroll
                for (int j = 0; j < 4; j++) S[i][j] = 0.f;

            #pragma unroll
            for (int ks = 0; ks < 4; ks++) {
                #pragma unroll
                for (int nt = 0; nt < 8; nt++) {
                    const char* pb = kh + (nt*8 + gr) * AROW + ks*32 + lq*2;
                    uint32_t bh[2];
                    bh[0] = *(const uint32_t*)pb;
                    bh[1] = *(const uint32_t*)(pb + 16);
                    MMA_F16(S[nt], qreg[ks], bh);
                }
            }

            if (s0 + 63 > q0 + wm) {
                #pragma unroll
                for (int nt = 0; nt < 8; nt++) {
                    int c0 = s0 + nt*8 + lq;
                    if (c0     > r0g) S[nt][0] = -1e30f;
                    if (c0 + 1 > r0g) S[nt][1] = -1e30f;
                    if (c0     > r1g) S[nt][2] = -1e30f;
                    if (c0 + 1 > r1g) S[nt][3] = -1e30f;
                }
            }

            float mx0 = -1e30f, mx1 = -1e30f;
            #pragma unroll
            for (int nt = 0; nt < 8; nt++) {
                mx0 = fmaxf(mx0, fmaxf(S[nt][0], S[nt][1]));
                mx1 = fmaxf(mx1, fmaxf(S[nt][2], S[nt][3]));
            }
            mx0 = fmaxf(mx0, __shfl_xor_sync(0xffffffffu, mx0, 1));
            mx0 = fmaxf(mx0, __shfl_xor_sync(0xffffffffu, mx0, 2));
            mx1 = fmaxf(mx1, __shfl_xor_sync(0xffffffffu, mx1, 1));
            mx1 = fmaxf(mx1, __shfl_xor_sync(0xffffffffu, mx1, 2));
            float mn0 = fmaxf(m0, mx0), mn1 = fmaxf(m1, mx1);
            float a0 = exp2f(m0 - mn0), a1 = exp2f(m1 - mn1);

            float sum0 = 0.f, sum1 = 0.f;
            uint32_t pH[8][2];
            #pragma unroll
            for (int nt = 0; nt < 8; nt++) {
                // h2exp2: one MUFU per pair; masked lanes -> -inf -> exp2 = 0
                __half2 e01 = h2exp2(__floats2half2_rn(S[nt][0] - mn0, S[nt][1] - mn0));
                __half2 e23 = h2exp2(__floats2half2_rn(S[nt][2] - mn1, S[nt][3] - mn1));
                pH[nt][0] = *(uint32_t*)&e01;
                pH[nt][1] = *(uint32_t*)&e23;
                float2 f01 = __half22float2(e01);
                float2 f23 = __half22float2(e23);
                sum0 += f01.x + f01.y;
                sum1 += f23.x + f23.y;
            }
            sum0 += __shfl_xor_sync(0xffffffffu, sum0, 1);
            sum0 += __shfl_xor_sync(0xffffffffu, sum0, 2);
            sum1 += __shfl_xor_sync(0xffffffffu, sum1, 1);
            sum1 += __shfl_xor_sync(0xffffffffu, sum1, 2);

            m0 = mn0; m1 = mn1;
            l0 = l0 * a0 + sum0;
            l1 = l1 * a1 + sum1;
            #pragma unroll
            for (int nt = 0; nt < 8; nt++) {
                O[nt][0] *= a0; O[nt][1] *= a0;
                O[nt][2] *= a1; O[nt][3] *= a1;
            }

            #pragma unroll
            for (int ks = 0; ks < 4; ks++) {
                uint32_t aH[4] = { pH[2*ks][0], pH[2*ks][1], pH[2*ks+1][0], pH[2*ks+1][1] };
                uint32_t bv[8][2];
                #pragma unroll
                for (int ntp = 0; ntp < 4; ntp++) {
                    uint32_t addr = vbase + (uint32_t)(ks*16*AROW + ntp*32);
                    LDSM_X4_TRANS(bv[2*ntp][0], bv[2*ntp][1], bv[2*ntp+1][0], bv[2*ntp+1][1], addr);
                }
                #pragma unroll
                for (int nt = 0; nt < 8; nt++)
                    MMA_F16(O[nt], aH, bv[nt]);
            }
        }

        if (kt + 2 < nkt) {
            load_att_stage(sq + QREG + (size_t)((kt + 2) % ASTG) * STAGE2, b, h, kt + 2, tid);
            asm volatile("cp.async.commit_group;" ::: "memory");
        }
    }

    float inv0 = 1.f / l0, inv1 = 1.f / l1;
    size_t t0 = (size_t)(b*SEQ + q0 + wm + gr) * DMODEL + h*64;
    size_t t1 = t0 + 8 * DMODEL;
    #pragma unroll
    for (int nt = 0; nt < 8; nt++) {
        int c0 = nt*8 + lq;
        *(__half2*)&g_Zhi[t0 + c0] = __floats2half2_rn(O[nt][0] * inv0, O[nt][1] * inv0);
        *(__half2*)&g_Zhi[t1 + c0] = __floats2half2_rn(O[nt][2] * inv1, O[nt][3] * inv1);
    }
}

// ---------------------------------------------------------------------------
extern "C" void kernel_launch(void* const* d_in, const int* in_sizes, int n_in,
                              void* d_out, int out_size)
{
    const float* resid = (const float*)d_in[0];
    const float* WQ    = (const float*)d_in[1];
    const float* WK    = (const float*)d_in[2];
    const float* WV    = (const float*)d_in[3];
    const float* Wout  = (const float*)d_in[4];
    const float* bout  = (const float*)d_in[5];
    float* out = (float*)d_out;

    cudaFuncSetAttribute(qkv_tc_kernel, cudaFuncAttributeMaxDynamicSharedMemorySize, GEMM_SMEM);
    cudaFuncSetAttribute(out_tc_kernel, cudaFuncAttributeMaxDynamicSharedMemorySize, GEMM_SMEM);
    cudaFuncSetAttribute(attn2_kernel,  cudaFuncAttributeMaxDynamicSharedMemorySize, ATT2_SMEM);

    conv_resid<<<NTOK*DMODEL/4/256, 256>>>(resid);
    conv_W4<<<dim3(32, 32, 4), dim3(32, 32)>>>(WQ, WK, WV, Wout);

    qkv_tc_kernel<<<dim3(DMODEL/128, NTOK/128, 3), 256, GEMM_SMEM>>>();

    attn2_kernel<<<dim3(SEQ/128, NHEAD, BATCH), 256, ATT2_SMEM>>>();

    out_tc_kernel<<<dim3(DMODEL/128, NTOK/128, 1), 256, GEMM_SMEM>>>(bout, out);
}

// round 16
// speedup vs baseline: 1.0207x; 1.0207x over previous
#include <cuda_runtime.h>
#include <cuda_fp16.h>
#include <cstdint>

#define BATCH 4
#define SEQ   2048
#define DMODEL 1024
#define NHEAD 16
#define DHEAD 64
#define NTOK  (BATCH*SEQ)   // 8192
#define MM    (DMODEL*DMODEL)
#define LOG2E 1.44269504088896f

// ---------------- scratch (__device__ globals: allocation-free) ----------------
__device__ __align__(16) __half g_Ahi[NTOK*DMODEL];
__device__ __align__(16) __half g_WhT[4*MM];          // [N,K] transposed fp16
__device__ __align__(16) __half g_Qhi[NTOK*DMODEL];   // pre-scaled by 0.125*log2(e)
__device__ __align__(16) __half g_Khi[NTOK*DMODEL];
__device__ __align__(16) __half g_Vhi[NTOK*DMODEL];
__device__ __align__(16) __half g_Zhi[NTOK*DMODEL];

__device__ __forceinline__ uint32_t smem_u32(const void* p) {
    uint32_t a;
    asm("{ .reg .u64 t; cvta.to.shared.u64 t, %1; cvt.u32.u64 %0, t; }" : "=r"(a) : "l"(p));
    return a;
}

#define MMA_F16(acc, a, b) \
    asm volatile("mma.sync.aligned.m16n8k16.row.col.f32.f16.f16.f32 " \
        "{%0,%1,%2,%3}, {%4,%5,%6,%7}, {%8,%9}, {%0,%1,%2,%3};" \
        : "+f"((acc)[0]), "+f"((acc)[1]), "+f"((acc)[2]), "+f"((acc)[3]) \
        : "r"((a)[0]), "r"((a)[1]), "r"((a)[2]), "r"((a)[3]), "r"((b)[0]), "r"((b)[1]))

#define LDSM_X4_TRANS(r0, r1, r2, r3, addr) \
    asm volatile("ldmatrix.sync.aligned.m8n8.x4.trans.shared.b16 {%0,%1,%2,%3}, [%4];" \
        : "=r"(r0), "=r"(r1), "=r"(r2), "=r"(r3) : "r"(addr))

#define CPA16(dst, src) \
    asm volatile("cp.async.cg.shared.global [%0], [%1], 16;" :: "r"(dst), "l"(src) : "memory")

// ---------------- conversion kernels ----------------
__global__ void __launch_bounds__(256) conv_resid(const float* __restrict__ src) {
    int i = blockIdx.x * 256 + threadIdx.x;
    float4 v = ((const float4*)src)[i];
    ((__half2*)g_Ahi)[2*i]   = __floats2half2_rn(v.x, v.y);
    ((__half2*)g_Ahi)[2*i+1] = __floats2half2_rn(v.z, v.w);
}

// All 4 weights in one launch: blockIdx.z = widx; widx==3 applies [dh,h,d] row remap.
__global__ void __launch_bounds__(1024) conv_W4(const float* __restrict__ WQ,
                                                const float* __restrict__ WK,
                                                const float* __restrict__ WV,
                                                const float* __restrict__ WO) {
    __shared__ float t[32][33];
    int widx = blockIdx.z;
    const float* src = (widx == 0) ? WQ : (widx == 1) ? WK : (widx == 2) ? WV : WO;
    int tx = threadIdx.x, ty = threadIdx.y;
    int k = blockIdx.y * 32 + ty, n = blockIdx.x * 32 + tx;
    int sk = (widx == 3) ? ((k & 63) * 16 + (k >> 6)) : k;
    t[ty][tx] = src[sk * DMODEL + n];
    __syncthreads();
    int n2 = blockIdx.x * 32 + ty, k2 = blockIdx.y * 32 + tx;
    g_WhT[(size_t)widx * MM + (size_t)n2 * DMODEL + k2] = __float2half_rn(t[tx][ty]);
}

// ---------------- 1-pass fp16 HMMA GEMM: C = alpha*(A@Bh^T), KC=64 ----------------
#define KC    64
#define NCH   (DMODEL / KC)            // 16
#define NSTG  3
#define ROWB  144                      // 128 data + 16 pad
#define TILE_B (128 * ROWB)            // 18432
#define STG_B  (2 * TILE_B)            // A, B
#define GEMM_SMEM (NSTG * STG_B)       // 110592

__device__ __forceinline__ void load_tile(uint32_t sdst, const __half* __restrict__ g,
                                          int row0, int k0, int tid) {
    const char* gb = (const char*)(g + (size_t)row0 * DMODEL + k0);
    #pragma unroll
    for (int i = 0; i < 4; i++) {
        int id = i * 256 + tid;
        int r = id >> 3, c = id & 7;
        uint32_t sd = sdst + (uint32_t)(r * ROWB + c * 16);
        const char* gp = gb + (size_t)r * (DMODEL * 2) + c * 16;
        CPA16(sd, gp);
    }
}

// OUTMODE 0: fp32 C + bias; 2: fp16 output. Single-sync multistage mainloop.
template<int OUTMODE>
__device__ __forceinline__ void gemm_hmma(const __half* __restrict__ A,
                                          const __half* __restrict__ Bh,
                                          float* __restrict__ C,
                                          const float* __restrict__ bias,
                                          __half* __restrict__ Chi,
                                          float alpha)
{
    extern __shared__ char sm[];
    uint32_t sbase = smem_u32(sm);

    int tid  = threadIdx.x;
    int wid  = tid >> 5, lane = tid & 31;
    int gr   = lane >> 2;
    int lc2  = (lane & 3) * 2;
    int wm   = (wid & 3) * 32;
    int wn   = (wid >> 2) * 64;
    int brow = blockIdx.y * 128;
    int bcol = blockIdx.x * 128;

    float acc[2][8][4];
    #pragma unroll
    for (int i = 0; i < 2; i++)
        #pragma unroll
        for (int j = 0; j < 8; j++)
            #pragma unroll
            for (int q = 0; q < 4; q++) acc[i][j][q] = 0.f;

    #pragma unroll
    for (int s = 0; s < NSTG - 1; s++) {
        uint32_t stg = sbase + s * STG_B;
        int k0 = s * KC;
        load_tile(stg,          A,  brow, k0, tid);
        load_tile(stg + TILE_B, Bh, bcol, k0, tid);
        asm volatile("cp.async.commit_group;" ::: "memory");
    }

    for (int c = 0; c < NCH; c++) {
        int rem = NCH - 1 - c;
        if (rem >= 1) asm volatile("cp.async.wait_group 1;" ::: "memory");
        else          asm volatile("cp.async.wait_group 0;" ::: "memory");
        __syncthreads();

        const char* stg = sm + (size_t)(c % NSTG) * STG_B;
        const char* pA  = stg;
        const char* pBh = stg + TILE_B;

        #pragma unroll
        for (int ks = 0; ks < 4; ks++) {
            int k0b = ks * 32;
            uint32_t ah[2][4], bh[8][2];
            #pragma unroll
            for (int mt = 0; mt < 2; mt++) {
                const char* p = pA + (wm + mt*16 + gr) * ROWB + k0b + lc2*2;
                ah[mt][0] = *(const uint32_t*)p;
                ah[mt][1] = *(const uint32_t*)(p + 8*ROWB);
                ah[mt][2] = *(const uint32_t*)(p + 16);
                ah[mt][3] = *(const uint32_t*)(p + 8*ROWB + 16);
            }
            #pragma unroll
            for (int nt = 0; nt < 8; nt++) {
                const char* p = pBh + (wn + nt*8 + gr) * ROWB + k0b + lc2*2;
                bh[nt][0] = *(const uint32_t*)p;
                bh[nt][1] = *(const uint32_t*)(p + 16);
            }
            #pragma unroll
            for (int mt = 0; mt < 2; mt++)
                #pragma unroll
                for (int nt = 0; nt < 8; nt++)
                    MMA_F16(acc[mt][nt], ah[mt], bh[nt]);
        }

        int cn = c + NSTG - 1;
        if (cn < NCH) {
            uint32_t stg2 = sbase + (cn % NSTG) * STG_B;
            int k0 = cn * KC;
            load_tile(stg2,          A,  brow, k0, tid);
            load_tile(stg2 + TILE_B, Bh, bcol, k0, tid);
            asm volatile("cp.async.commit_group;" ::: "memory");
        }
    }

    #pragma unroll
    for (int mt = 0; mt < 2; mt++) {
        int r0 = brow + wm + mt*16 + gr;
        #pragma unroll
        for (int nt = 0; nt < 8; nt++) {
            int c0 = bcol + wn + nt*8 + lc2;
            if (OUTMODE == 0) {
                float bx = bias[c0], by = bias[c0 + 1];
                float2 v0, v1;
                v0.x = acc[mt][nt][0] * alpha + bx;
                v0.y = acc[mt][nt][1] * alpha + by;
                v1.x = acc[mt][nt][2] * alpha + bx;
                v1.y = acc[mt][nt][3] * alpha + by;
                *(float2*)&C[(size_t)r0 * DMODEL + c0]       = v0;
                *(float2*)&C[(size_t)(r0 + 8) * DMODEL + c0] = v1;
            } else {
                *(__half2*)&Chi[(size_t)r0 * DMODEL + c0] =
                    __floats2half2_rn(acc[mt][nt][0] * alpha, acc[mt][nt][1] * alpha);
                *(__half2*)&Chi[(size_t)(r0+8) * DMODEL + c0] =
                    __floats2half2_rn(acc[mt][nt][2] * alpha, acc[mt][nt][3] * alpha);
            }
        }
    }
}

__global__ void __launch_bounds__(256, 2) qkv_tc_kernel() {
    int z = blockIdx.z;
    const __half* Bh = g_WhT + (size_t)z * MM;
    __half* Ch = (z == 0) ? g_Qhi : (z == 1) ? g_Khi : g_Vhi;
    float alpha = (z == 0) ? (0.125f * LOG2E) : 1.0f;
    gemm_hmma<2>(g_Ahi, Bh, nullptr, nullptr, Ch, alpha);
}

__global__ void __launch_bounds__(256, 2) out_tc_kernel(const float* __restrict__ bias,
                                                        float* __restrict__ out) {
    gemm_hmma<0>(g_Zhi, g_WhT + 3ull*MM, out, bias, nullptr, 1.0f);
}

// ---------------- fp16 flash attention (causal); exp2f softmax, Q in registers ----------------
#define AROW 144
#define QREG (128 * AROW)
#define TREG (64 * AROW)
#define STAGE2 (2 * TREG)                  // Khi, Vhi (natural layout)
#define ASTG 3
#define ATT2_SMEM (QREG + ASTG*STAGE2)     // 73728

__device__ __forceinline__ void load_att_stage(uint32_t dst, int b, int h, int kt, int tid) {
    int s0 = kt * 64;
    const char* gkh = (const char*)g_Khi + ((size_t)(b*SEQ + s0) * DMODEL + h*64) * 2;
    const char* gvh = (const char*)g_Vhi + ((size_t)(b*SEQ + s0) * DMODEL + h*64) * 2;
    #pragma unroll
    for (int i = 0; i < 2; i++) {
        int idx = i * 256 + tid;
        int r = idx >> 3, c = idx & 7;
        uint32_t off = (uint32_t)(r * AROW + c * 16);
        CPA16(dst + off,        gkh + (size_t)r * (DMODEL*2) + c*16);
        CPA16(dst + TREG + off, gvh + (size_t)r * (DMODEL*2) + c*16);
    }
}

__global__ void __launch_bounds__(256, 2) attn2_kernel() {
    extern __shared__ char sm[];
    uint32_t sq = smem_u32(sm);

    int tid = threadIdx.x, wid = tid >> 5, lane = tid & 31;
    int gr = lane >> 2, lq = (lane & 3) * 2;
    int qt = (gridDim.x - 1) - blockIdx.x;   // heaviest CTAs first
    int h = blockIdx.y, b = blockIdx.z;
    int q0 = qt * 128, wm = wid * 16;
    int nkt = 2*qt + 2;

    uint32_t vloff = (uint32_t)(((lane & 7) + ((lane >> 3) & 1) * 8) * AROW + (lane >> 4) * 16);

    {
        const char* gqh = (const char*)g_Qhi + ((size_t)(b*SEQ + q0) * DMODEL + h*64) * 2;
        #pragma unroll
        for (int i = 0; i < 4; i++) {
            int idx = i * 256 + tid;
            int r = idx >> 3, c = idx & 7;
            uint32_t off = (uint32_t)(r * AROW + c * 16);
            CPA16(sq + off, gqh + (size_t)r * (DMODEL*2) + c*16);
        }
    }
    load_att_stage(sq + QREG, b, h, 0, tid);
    asm volatile("cp.async.commit_group;" ::: "memory");
    if (nkt > 1) {
        load_att_stage(sq + QREG + STAGE2, b, h, 1, tid);
        asm volatile("cp.async.commit_group;" ::: "memory");
    }

    float m0 = -1e30f, m1 = -1e30f, l0 = 0.f, l1 = 0.f;
    float O[8][4];
    #pragma unroll
    for (int i = 0; i < 8; i++)
        #pragma unroll
        for (int j = 0; j < 4; j++) O[i][j] = 0.f;

    uint32_t qreg[4][4];   // Q fragments, loop-invariant (loaded at kt==0)
    int r0g = q0 + wm + gr, r1g = r0g + 8;

    for (int kt = 0; kt < nkt; kt++) {
        int rem = nkt - 1 - kt;
        if (rem >= 1) asm volatile("cp.async.wait_group 1;" ::: "memory");
        else          asm volatile("cp.async.wait_group 0;" ::: "memory");
        __syncthreads();

        if (kt == 0) {
            #pragma unroll
            for (int ks = 0; ks < 4; ks++) {
                const char* pa = sm + (wm + gr) * AROW + ks*32 + lq*2;
                qreg[ks][0] = *(const uint32_t*)pa;
                qreg[ks][1] = *(const uint32_t*)(pa + 8*AROW);
                qreg[ks][2] = *(const uint32_t*)(pa + 16);
                qreg[ks][3] = *(const uint32_t*)(pa + 8*AROW + 16);
            }
        }

        int s0 = kt * 64;
        if (s0 <= q0 + wm + 15) {
            const char* st   = sm + QREG + (size_t)(kt % ASTG) * STAGE2;
            const char* kh   = st;
            uint32_t vbase   = sq + QREG + (uint32_t)(kt % ASTG) * STAGE2 + TREG + vloff;

            float S[8][4];
            #pragma unroll
            for (int i = 0; i < 8; i++)
                #pragma unroll
                for (int j = 0; j < 4; j++) S[i][j] = 0.f;

            #pragma unroll
            for (int ks = 0; ks < 4; ks++) {
                #pragma unroll
                for (int nt = 0; nt < 8; nt++) {
                    const char* pb = kh + (nt*8 + gr) * AROW + ks*32 + lq*2;
                    uint32_t bh[2];
                    bh[0] = *(const uint32_t*)pb;
                    bh[1] = *(const uint32_t*)(pb + 16);
                    MMA_F16(S[nt], qreg[ks], bh);
                }
            }

            if (s0 + 63 > q0 + wm) {
                #pragma unroll
                for (int nt = 0; nt < 8; nt++) {
                    int c0 = s0 + nt*8 + lq;
                    if (c0     > r0g) S[nt][0] = -1e30f;
                    if (c0 + 1 > r0g) S[nt][1] = -1e30f;
                    if (c0     > r1g) S[nt][2] = -1e30f;
                    if (c0 + 1 > r1g) S[nt][3] = -1e30f;
                }
            }

            float mx0 = -1e30f, mx1 = -1e30f;
            #pragma unroll
            for (int nt = 0; nt < 8; nt++) {
                mx0 = fmaxf(mx0, fmaxf(S[nt][0], S[nt][1]));
                mx1 = fmaxf(mx1, fmaxf(S[nt][2], S[nt][3]));
            }
            mx0 = fmaxf(mx0, __shfl_xor_sync(0xffffffffu, mx0, 1));
            mx0 = fmaxf(mx0, __shfl_xor_sync(0xffffffffu, mx0, 2));
            mx1 = fmaxf(mx1, __shfl_xor_sync(0xffffffffu, mx1, 1));
            mx1 = fmaxf(mx1, __shfl_xor_sync(0xffffffffu, mx1, 2));
            float mn0 = fmaxf(m0, mx0), mn1 = fmaxf(m1, mx1);
            float a0 = exp2f(m0 - mn0), a1 = exp2f(m1 - mn1);

            float sum0 = 0.f, sum1 = 0.f;
            uint32_t pH[8][2];
            #pragma unroll
            for (int nt = 0; nt < 8; nt++) {
                float p0 = exp2f(S[nt][0] - mn0);
                float p1 = exp2f(S[nt][1] - mn0);
                float p2 = exp2f(S[nt][2] - mn1);
                float p3 = exp2f(S[nt][3] - mn1);
                sum0 += p0 + p1; sum1 += p2 + p3;
                __half2 h01 = __floats2half2_rn(p0, p1);
                __half2 h23 = __floats2half2_rn(p2, p3);
                pH[nt][0] = *(uint32_t*)&h01;
                pH[nt][1] = *(uint32_t*)&h23;
            }
            sum0 += __shfl_xor_sync(0xffffffffu, sum0, 1);
            sum0 += __shfl_xor_sync(0xffffffffu, sum0, 2);
            sum1 += __shfl_xor_sync(0xffffffffu, sum1, 1);
            sum1 += __shfl_xor_sync(0xffffffffu, sum1, 2);

            m0 = mn0; m1 = mn1;
            l0 = l0 * a0 + sum0;
            l1 = l1 * a1 + sum1;
            #pragma unroll
            for (int nt = 0; nt < 8; nt++) {
                O[nt][0] *= a0; O[nt][1] *= a0;
                O[nt][2] *= a1; O[nt][3] *= a1;
            }

            #pragma unroll
            for (int ks = 0; ks < 4; ks++) {
                uint32_t aH[4] = { pH[2*ks][0], pH[2*ks][1], pH[2*ks+1][0], pH[2*ks+1][1] };
                uint32_t bv[8][2];
                #pragma unroll
                for (int ntp = 0; ntp < 4; ntp++) {
                    uint32_t addr = vbase + (uint32_t)(ks*16*AROW + ntp*32);
                    LDSM_X4_TRANS(bv[2*ntp][0], bv[2*ntp][1], bv[2*ntp+1][0], bv[2*ntp+1][1], addr);
                }
                #pragma unroll
                for (int nt = 0; nt < 8; nt++)
                    MMA_F16(O[nt], aH, bv[nt]);
            }
        }

        if (kt + 2 < nkt) {
            load_att_stage(sq + QREG + (size_t)((kt + 2) % ASTG) * STAGE2, b, h, kt + 2, tid);
            asm volatile("cp.async.commit_group;" ::: "memory");
        }
    }

    float inv0 = 1.f / l0, inv1 = 1.f / l1;
    size_t t0 = (size_t)(b*SEQ + q0 + wm + gr) * DMODEL + h*64;
    size_t t1 = t0 + 8 * DMODEL;
    #pragma unroll
    for (int nt = 0; nt < 8; nt++) {
        int c0 = nt*8 + lq;
        *(__half2*)&g_Zhi[t0 + c0] = __floats2half2_rn(O[nt][0] * inv0, O[nt][1] * inv0);
        *(__half2*)&g_Zhi[t1 + c0] = __floats2half2_rn(O[nt][2] * inv1, O[nt][3] * inv1);
    }
}

// ---------------------------------------------------------------------------
extern "C" void kernel_launch(void* const* d_in, const int* in_sizes, int n_in,
                              void* d_out, int out_size)
{
    const float* resid = (const float*)d_in[0];
    const float* WQ    = (const float*)d_in[1];
    const float* WK    = (const float*)d_in[2];
    const float* WV    = (const float*)d_in[3];
    const float* Wout  = (const float*)d_in[4];
    const float* bout  = (const float*)d_in[5];
    float* out = (float*)d_out;

    cudaFuncSetAttribute(qkv_tc_kernel, cudaFuncAttributeMaxDynamicSharedMemorySize, GEMM_SMEM);
    cudaFuncSetAttribute(out_tc_kernel, cudaFuncAttributeMaxDynamicSharedMemorySize, GEMM_SMEM);
    cudaFuncSetAttribute(attn2_kernel,  cudaFuncAttributeMaxDynamicSharedMemorySize, ATT2_SMEM);

    conv_resid<<<NTOK*DMODEL/4/256, 256>>>(resid);
    conv_W4<<<dim3(32, 32, 4), dim3(32, 32)>>>(WQ, WK, WV, Wout);

    qkv_tc_kernel<<<dim3(DMODEL/128, NTOK/128, 3), 256, GEMM_SMEM>>>();

    attn2_kernel<<<dim3(SEQ/128, NHEAD, BATCH), 256, ATT2_SMEM>>>();

    out_tc_kernel<<<dim3(DMODEL/128, NTOK/128, 1), 256, GEMM_SMEM>>>(bout, out);
}